// round 2
// baseline (speedup 1.0000x reference)
#include <cuda_runtime.h>
#include <cuda_bf16.h>
#include <cstdint>

// Problem constants
#define NB   16
#define TT   2048
#define FIN  64
#define NN   24
#define HH   64
#define BT   (NB*TT)            // 32768
#define NH   (NN*HH)            // 1536
#define TOK  16                 // tokens per block
#define GRID (BT/TOK)           // 2048
#define ALPHA 0.2f
#define NEGINF (-9.0e15f)

// ---------------- precomputed weights (device globals; no allocs) ----------------
__device__ float g_Wc[FIN*NH];   // [f][col]  col = n*64+k : Wc = Wp @ blockdiag(W)
__device__ float g_bc[NH];       // bc[col] = sum_j bp[n*64+j]*W[j][k]
__device__ float g_ca1[FIN*NN];  // [f][n] = sum_j Wp[f][n*64+j]*wa1[j]
__device__ float g_ca2[FIN*NN];
__device__ float g_cb1[NN];
__device__ float g_cb2[NN];
__device__ float g_wa1[FIN];     // W @ a1
__device__ float g_wa2[FIN];     // W @ a2

// ---------------- packed fp32x2 helpers (sm_100+ dual-issue fp32) ----------------
__device__ __forceinline__ unsigned long long pack2(float lo, float hi) {
    unsigned long long r;
    asm("mov.b64 %0, {%1, %2};" : "=l"(r) : "f"(lo), "f"(hi));
    return r;
}
__device__ __forceinline__ unsigned long long packbb(float v) {
    unsigned long long r;
    asm("mov.b64 %0, {%1, %1};" : "=l"(r) : "f"(v));
    return r;
}
__device__ __forceinline__ void unpack2(unsigned long long v, float& lo, float& hi) {
    asm("mov.b64 {%0, %1}, %2;" : "=f"(lo), "=f"(hi) : "l"(v));
}
#define FMA2(acc, a, b) asm("fma.rn.f32x2 %0, %1, %2, %0;" : "+l"(acc) : "l"(a), "l"(b))

// ---------------- precompute kernel 1: wa1/wa2, bc, cb ----------------
__global__ void k_pre1(const float* __restrict__ W, const float* __restrict__ a,
                       const float* __restrict__ bp) {
    __shared__ float swa1[FIN], swa2[FIN];
    int tid = threadIdx.x;
    if (tid < FIN) {
        float s1 = 0.f, s2 = 0.f;
        #pragma unroll 8
        for (int k = 0; k < HH; k++) {
            float wv = W[tid*HH + k];
            s1 = fmaf(wv, a[k], s1);
            s2 = fmaf(wv, a[HH + k], s2);
        }
        g_wa1[tid] = s1; g_wa2[tid] = s2;
        swa1[tid] = s1;  swa2[tid] = s2;
    }
    __syncthreads();
    for (int o = tid; o < NH; o += 256) {
        int n = o >> 6, k = o & 63;
        float s = 0.f;
        for (int j = 0; j < HH; j++) s = fmaf(bp[n*HH + j], W[j*HH + k], s);
        g_bc[o] = s;
    }
    if (tid < NN) {
        float s1 = 0.f, s2 = 0.f;
        for (int j = 0; j < HH; j++) {
            float b = bp[tid*HH + j];
            s1 = fmaf(b, swa1[j], s1);
            s2 = fmaf(b, swa2[j], s2);
        }
        g_cb1[tid] = s1; g_cb2[tid] = s2;
    }
}

// ---------------- precompute kernel 2: Wc rows + ca1/ca2 ----------------
__global__ void k_pre2(const float* __restrict__ Wp, const float* __restrict__ W) {
    __shared__ float sW[HH*HH];    // 16KB
    __shared__ float sWp[NH];      // 6KB (one f-row of Wp)
    int f = blockIdx.x, tid = threadIdx.x;
    for (int i = tid; i < HH*HH; i += 256) sW[i] = W[i];
    for (int i = tid; i < NH;    i += 256) sWp[i] = Wp[f*NH + i];
    __syncthreads();
    for (int o = tid; o < NH; o += 256) {
        int n = o >> 6, k = o & 63;
        float s = 0.f;
        #pragma unroll 8
        for (int j = 0; j < HH; j++) s = fmaf(sWp[n*HH + j], sW[j*HH + k], s);
        g_Wc[f*NH + o] = s;
    }
    if (tid < NN) {
        float s1 = 0.f, s2 = 0.f;
        for (int j = 0; j < HH; j++) {
            float wv = sWp[tid*HH + j];
            s1 = fmaf(wv, g_wa1[j], s1);
            s2 = fmaf(wv, g_wa2[j], s2);
        }
        g_ca1[f*NN + tid] = s1;
        g_ca2[f*NN + tid] = s2;
    }
}

// ---------------- main fused kernel ----------------
// smem layout (bytes):
//  sX    @ 0      : 64x16 f32 transposed (f-major, token pairs contiguous)  4096
//  sCa1  @ 4096   : 1536 f32                                                6144
//  sCa2  @ 10240  : 1536 f32                                                6144
//  sCb1  @ 16384  : 24 f32                                                  96
//  sCb2  @ 16480  : 24 f32                                                  96
//  sF1   @ 16576  : 16x24 f32                                               1536
//  sF2   @ 18112  : 16x24 f32                                               1536
//  sAdj  @ 19648  : 576 i32                                                 2304
//  sAttn @ 21952  : 16x24x24 f32                                            36864
//  sWh   @ 58816  : 16x1536 f32                                             98304
// total = 157120
#define SMEM_BYTES 157120

__global__ void __launch_bounds__(256, 1)
k_main(const float* __restrict__ x, const int* __restrict__ adj,
       float* __restrict__ out) {
    extern __shared__ char smem[];
    float* sX    = (float*)(smem);
    float* sCa1  = (float*)(smem + 4096);
    float* sCa2  = (float*)(smem + 10240);
    float* sCb1  = (float*)(smem + 16384);
    float* sCb2  = (float*)(smem + 16480);
    float* sF1   = (float*)(smem + 16576);
    float* sF2   = (float*)(smem + 18112);
    int*   sAdj  = (int*)  (smem + 19648);
    float* sAttn = (float*)(smem + 21952);
    float* sWh   = (float*)(smem + 58816);

    const int tid = threadIdx.x;
    const int tok0 = blockIdx.x * TOK;
    const float* xb = x + (size_t)tok0 * FIN;

    // ---- load x (transposed), ca/cb, adj ----
    for (int i = tid; i < TOK*FIN; i += 256) {
        int t = i >> 6, f = i & 63;
        sX[f*TOK + t] = xb[i];
    }
    for (int i = tid; i < FIN*NN; i += 256) { sCa1[i] = g_ca1[i]; sCa2[i] = g_ca2[i]; }
    if (tid < NN) { sCb1[tid] = g_cb1[tid]; sCb2[tid] = g_cb2[tid]; }
    for (int i = tid; i < NN*NN; i += 256) sAdj[i] = adj[i];
    __syncthreads();

    // ---- f1/f2: 16 tokens x 24 nodes, 64-dot each ----
    for (int task = tid; task < TOK*NN; task += 256) {
        int t = task / NN, n = task % NN;
        float s1 = sCb1[n], s2 = sCb2[n];
        #pragma unroll 8
        for (int f = 0; f < FIN; f++) {
            float xv = sX[f*TOK + t];
            s1 = fmaf(xv, sCa1[f*NN + n], s1);
            s2 = fmaf(xv, sCa2[f*NN + n], s2);
        }
        sF1[t*NN + n] = s1;
        sF2[t*NN + n] = s2;
    }
    __syncthreads();

    // ---- softmax rows: e = mask(lrelu(f1_i + f2_j)), softmax over j ----
    for (int task = tid; task < TOK*NN; task += 256) {
        int t = task / NN, i = task % NN;
        float f1v = sF1[t*NN + i];
        float ev[NN];
        float m = -3.0e38f;
        #pragma unroll
        for (int j = 0; j < NN; j++) {
            float e = f1v + sF2[t*NN + j];
            e = e > 0.f ? e : ALPHA * e;
            e = (sAdj[i*NN + j] > 0) ? e : NEGINF;
            ev[j] = e;
            m = fmaxf(m, e);
        }
        float sum = 0.f;
        #pragma unroll
        for (int j = 0; j < NN; j++) { float p = __expf(ev[j] - m); ev[j] = p; sum += p; }
        float inv = 1.0f / sum;
        #pragma unroll
        for (int j = 0; j < NN; j++) sAttn[t*576 + i*NN + j] = ev[j] * inv;
    }
    // (phase-1 below only reads sX / writes sWh; no sync needed before it)

    // ---- phase 1: Wh[16][1536] = x @ Wc + bc, register tile 8 tok x 6 cols ----
    {
        const int tt = tid >> 7;     // 0..1 -> tokens tt*8..tt*8+7
        const int cc = tid & 127;    // base column
        #pragma unroll 1
        for (int chunk = 0; chunk < 2; chunk++) {
            const int colb = cc + 768*chunk;
            unsigned long long acc[4][6];
            #pragma unroll
            for (int u = 0; u < 6; u++) {
                float bcv = g_bc[colb + 128*u];
                unsigned long long b2 = packbb(bcv);
                #pragma unroll
                for (int p = 0; p < 4; p++) acc[p][u] = b2;
            }
            #pragma unroll 4
            for (int f = 0; f < FIN; f++) {
                unsigned long long xp[4];
                #pragma unroll
                for (int p = 0; p < 4; p++)
                    xp[p] = *(const unsigned long long*)&sX[f*TOK + tt*8 + 2*p];
                #pragma unroll
                for (int u = 0; u < 6; u++) {
                    float wv = g_Wc[f*NH + colb + 128*u];
                    unsigned long long wp = packbb(wv);
                    #pragma unroll
                    for (int p = 0; p < 4; p++) FMA2(acc[p][u], xp[p], wp);
                }
            }
            #pragma unroll
            for (int p = 0; p < 4; p++) {
                #pragma unroll
                for (int u = 0; u < 6; u++) {
                    int col = colb + 128*u;
                    int t0 = tt*8 + 2*p;
                    float lo, hi; unpack2(acc[p][u], lo, hi);
                    sWh[t0*NH + col]       = lo;
                    sWh[(t0+1)*NH + col]   = hi;
                }
            }
        }
    }
    __syncthreads();

    // ---- phase 2: out[t][k] = mean_i elu( sum_j attn[t][i][j]*Wh[t][j][k] ) ----
    {
        const int t = tid >> 4;      // 0..15 token
        const int g = tid & 15;      // k = g + 16q, q=0..3
        const float* whb = sWh + t*NH;
        unsigned long long whp[NN][2];
        #pragma unroll
        for (int j = 0; j < NN; j++) {
            float w0 = whb[j*HH + g];
            float w1 = whb[j*HH + g + 16];
            float w2 = whb[j*HH + g + 32];
            float w3 = whb[j*HH + g + 48];
            whp[j][0] = pack2(w0, w1);
            whp[j][1] = pack2(w2, w3);
        }
        float o0 = 0.f, o1 = 0.f, o2 = 0.f, o3 = 0.f;
        const float* arow = sAttn + t*576;
        #pragma unroll 1
        for (int i = 0; i < NN; i++) {
            unsigned long long s01 = 0ull, s23 = 0ull;  // bits 0 == (0.f, 0.f)
            #pragma unroll
            for (int j = 0; j < NN; j++) {
                unsigned long long ap = packbb(arow[i*NN + j]);
                FMA2(s01, ap, whp[j][0]);
                FMA2(s23, ap, whp[j][1]);
            }
            float v0, v1, v2, v3;
            unpack2(s01, v0, v1);
            unpack2(s23, v2, v3);
            o0 += (v0 > 0.f) ? v0 : (__expf(v0) - 1.f);
            o1 += (v1 > 0.f) ? v1 : (__expf(v1) - 1.f);
            o2 += (v2 > 0.f) ? v2 : (__expf(v2) - 1.f);
            o3 += (v3 > 0.f) ? v3 : (__expf(v3) - 1.f);
        }
        const float sc = 1.0f / (float)NN;
        float* ob = out + (size_t)(tok0 + t) * HH;
        ob[g]      = o0 * sc;
        ob[g + 16] = o1 * sc;
        ob[g + 32] = o2 * sc;
        ob[g + 48] = o3 * sc;
    }
}

// ---------------- launch ----------------
extern "C" void kernel_launch(void* const* d_in, const int* in_sizes, int n_in,
                              void* d_out, int out_size) {
    const float* x   = (const float*)d_in[0];
    const int*   adj = (const int*)  d_in[1];
    const float* Wp  = (const float*)d_in[2];
    const float* bp  = (const float*)d_in[3];
    const float* W   = (const float*)d_in[4];
    const float* a   = (const float*)d_in[5];
    float* out = (float*)d_out;

    k_pre1<<<1, 256>>>(W, a, bp);
    k_pre2<<<FIN, 256>>>(Wp, W);

    cudaFuncSetAttribute(k_main, cudaFuncAttributeMaxDynamicSharedMemorySize, SMEM_BYTES);
    k_main<<<GRID, 256, SMEM_BYTES>>>(x, adj, out);
}

// round 5
// speedup vs baseline: 1.4074x; 1.4074x over previous
#include <cuda_runtime.h>
#include <cuda_bf16.h>
#include <cstdint>

// Problem constants
#define NB   16
#define TT   2048
#define FIN  64
#define NN   24
#define HH   64
#define BT   (NB*TT)            // 32768
#define NH   (NN*HH)            // 1536
#define TOK  16                 // tokens per block
#define GRID (BT/TOK)           // 2048
#define THR  512
#define ALPHA 0.2f
#define NEGINF (-9.0e15f)

// ---------------- precomputed weights (device globals; no allocs) ----------------
__device__ __align__(16) float g_Wc[FIN*NH];   // [f][col], col = n*64+k : Wc = Wp @ blockdiag(W)
__device__ __align__(16) float g_bc[NH];       // bc[col] = sum_j bp[n*64+j]*W[j][k]
__device__ __align__(16) float g_ca1[FIN*NN];  // [f][n]
__device__ __align__(16) float g_ca2[FIN*NN];
__device__ float g_cb1[NN];
__device__ float g_cb2[NN];

// ---------------- packed fp32x2 helpers ----------------
__device__ __forceinline__ unsigned long long pack2(float lo, float hi) {
    unsigned long long r;
    asm("mov.b64 %0, {%1, %2};" : "=l"(r) : "f"(lo), "f"(hi));
    return r;
}
__device__ __forceinline__ unsigned long long packbb(float v) {
    unsigned long long r;
    asm("mov.b64 %0, {%1, %1};" : "=l"(r) : "f"(v));
    return r;
}
__device__ __forceinline__ void unpack2(unsigned long long v, float& lo, float& hi) {
    asm("mov.b64 {%0, %1}, %2;" : "=f"(lo), "=f"(hi) : "l"(v));
}
#define FMA2(acc, a, b) asm("fma.rn.f32x2 %0, %1, %2, %0;" : "+l"(acc) : "l"(a), "l"(b))

// ---------------- merged precompute: one launch, 64 blocks ----------------
// Block f: Wc row f, ca1/ca2 row f, bc cols [f*24, f*24+24); block 0 also cb1/cb2.
// W@a1 / W@a2 recomputed locally per block (trivial) to avoid a serial dependency launch.
__global__ void __launch_bounds__(256)
k_pre(const float* __restrict__ Wp, const float* __restrict__ bp,
      const float* __restrict__ W,  const float* __restrict__ a) {
    __shared__ float sW[HH*HH];    // 16KB
    __shared__ float sWp[NH];      // 6KB
    __shared__ float swa1[HH], swa2[HH];
    const int f = blockIdx.x, tid = threadIdx.x;
    for (int i = tid; i < HH*HH; i += 256) sW[i] = W[i];
    for (int i = tid; i < NH;    i += 256) sWp[i] = Wp[f*NH + i];
    __syncthreads();
    if (tid < HH) {
        float s1 = 0.f, s2 = 0.f;
        #pragma unroll 8
        for (int k = 0; k < HH; k++) {
            float wv = sW[tid*HH + k];
            s1 = fmaf(wv, a[k],      s1);
            s2 = fmaf(wv, a[HH + k], s2);
        }
        swa1[tid] = s1; swa2[tid] = s2;
    }
    __syncthreads();
    // Wc row f
    for (int o = tid; o < NH; o += 256) {
        int n = o >> 6, k = o & 63;
        float s = 0.f;
        #pragma unroll 8
        for (int j = 0; j < HH; j++) s = fmaf(sWp[n*HH + j], sW[j*HH + k], s);
        g_Wc[f*NH + o] = s;
    }
    // ca row f
    if (tid < NN) {
        float s1 = 0.f, s2 = 0.f;
        for (int j = 0; j < HH; j++) {
            float wv = sWp[tid*HH + j];
            s1 = fmaf(wv, swa1[j], s1);
            s2 = fmaf(wv, swa2[j], s2);
        }
        g_ca1[f*NN + tid] = s1;
        g_ca2[f*NN + tid] = s2;
    }
    // bc slice: 24 cols per block
    if (tid >= 32 && tid < 32 + NN) {
        int c = f*NN + (tid - 32);
        int n = c >> 6, k = c & 63;
        float s = 0.f;
        #pragma unroll 8
        for (int j = 0; j < HH; j++) s = fmaf(bp[n*HH + j], sW[j*HH + k], s);
        g_bc[c] = s;
    }
    // cb (block 0 only)
    if (f == 0 && tid >= 64 && tid < 64 + NN) {
        int n = tid - 64;
        float s1 = 0.f, s2 = 0.f;
        for (int j = 0; j < HH; j++) {
            float b = bp[n*HH + j];
            s1 = fmaf(b, swa1[j], s1);
            s2 = fmaf(b, swa2[j], s2);
        }
        g_cb1[n] = s1; g_cb2[n] = s2;
    }
}

// ---------------- main fused kernel ----------------
// smem layout (bytes), all 8B-aligned:
//  sX    @ 0      : 64x16 f32 transposed (f-major)        4096
//  sCa1  @ 4096   : 1536 f32                              6144
//  sCa2  @ 10240  : 1536 f32                              6144
//  sCb1  @ 16384  : 24 f32                                96
//  sCb2  @ 16480  : 24 f32                                96
//  sF1   @ 16576  : 16x24 f32                             1536
//  sF2   @ 18112  : 16x24 f32                             1536
//  sAdj  @ 19648  : 576 i32                               2304
//  sAttn @ 21952  : 16x24x24 f32                          36864
//  sWh   @ 58816  : 16x1536 f32                           98304
#define SMEM_BYTES 157120

__global__ void __launch_bounds__(THR, 1)
k_main(const float* __restrict__ x, const int* __restrict__ adj,
       float* __restrict__ out) {
    extern __shared__ char smem[];
    float* sX    = (float*)(smem);
    float* sCa1  = (float*)(smem + 4096);
    float* sCa2  = (float*)(smem + 10240);
    float* sCb1  = (float*)(smem + 16384);
    float* sCb2  = (float*)(smem + 16480);
    float* sF1   = (float*)(smem + 16576);
    float* sF2   = (float*)(smem + 18112);
    int*   sAdj  = (int*)  (smem + 19648);
    float* sAttn = (float*)(smem + 21952);
    float* sWh   = (float*)(smem + 58816);

    const int tid = threadIdx.x;
    const int tok0 = blockIdx.x * TOK;
    const float* xb = x + (size_t)tok0 * FIN;

    // ---- loads ----
    for (int i = tid; i < TOK*FIN; i += THR) {
        int t = i >> 6, f = i & 63;
        sX[f*TOK + t] = xb[i];
    }
    for (int i = tid; i < FIN*NN; i += THR) { sCa1[i] = g_ca1[i]; sCa2[i] = g_ca2[i]; }
    if (tid < NN) { sCb1[tid] = g_cb1[tid]; sCb2[tid] = g_cb2[tid]; }
    for (int i = tid; i < NN*NN; i += THR) sAdj[i] = adj[i];
    __syncthreads();

    // ---- f1/f2: 16 tokens x 24 nodes ----
    if (tid < TOK*NN) {
        int t = tid / NN, n = tid % NN;
        float s1 = sCb1[n], s2 = sCb2[n];
        #pragma unroll 8
        for (int f = 0; f < FIN; f++) {
            float xv = sX[f*TOK + t];
            s1 = fmaf(xv, sCa1[f*NN + n], s1);
            s2 = fmaf(xv, sCa2[f*NN + n], s2);
        }
        sF1[t*NN + n] = s1;
        sF2[t*NN + n] = s2;
    }
    __syncthreads();

    // ---- softmax rows ----
    if (tid < TOK*NN) {
        int t = tid / NN, i = tid % NN;
        float f1v = sF1[t*NN + i];
        float ev[NN];
        float m = -3.0e38f;
        #pragma unroll
        for (int j = 0; j < NN; j++) {
            float e = f1v + sF2[t*NN + j];
            e = e > 0.f ? e : ALPHA * e;
            e = (sAdj[i*NN + j] > 0) ? e : NEGINF;
            ev[j] = e;
            m = fmaxf(m, e);
        }
        float sum = 0.f;
        #pragma unroll
        for (int j = 0; j < NN; j++) { float p = __expf(ev[j] - m); ev[j] = p; sum += p; }
        float inv = 1.0f / sum;
        #pragma unroll
        for (int j = 0; j < NN; j++) sAttn[t*576 + i*NN + j] = ev[j] * inv;
    }
    // (phase-1 reads sX, writes sWh — no hazard with softmax; one sync after both)

    // ---- phase 1: Wh[16][1536] = x @ Wc + bc ----
    // 512 threads: tt = tid>>8 picks token half (8 tokens), cc = tid&255 picks an
    // even column pair base. Each thread: 8 tokens x 3 column-pairs, f32x2 packed
    // along columns. Per f: 3x LDG.64 (Wc), 8x LDS.32 bcast (x), 24 FMA2.
    {
        const int tt = tid >> 8;       // 0..1
        const int cc = tid & 255;      // column pair index
        const float* wc = g_Wc + 2*cc;
        unsigned long long acc[8][3];
        {
            unsigned long long b0 = *(const unsigned long long*)&g_bc[2*cc];
            unsigned long long b1 = *(const unsigned long long*)&g_bc[2*cc + 512];
            unsigned long long b2 = *(const unsigned long long*)&g_bc[2*cc + 1024];
            #pragma unroll
            for (int t = 0; t < 8; t++) { acc[t][0] = b0; acc[t][1] = b1; acc[t][2] = b2; }
        }
        const float* xrow = sX + tt*8;
        #pragma unroll 4
        for (int f = 0; f < FIN; f++) {
            unsigned long long wp0 = *(const unsigned long long*)(wc + (size_t)f*NH);
            unsigned long long wp1 = *(const unsigned long long*)(wc + (size_t)f*NH + 512);
            unsigned long long wp2 = *(const unsigned long long*)(wc + (size_t)f*NH + 1024);
            unsigned long long xbb[8];
            #pragma unroll
            for (int t = 0; t < 8; t++) xbb[t] = packbb(xrow[f*TOK + t]);
            #pragma unroll
            for (int t = 0; t < 8; t++) {
                FMA2(acc[t][0], xbb[t], wp0);
                FMA2(acc[t][1], xbb[t], wp1);
                FMA2(acc[t][2], xbb[t], wp2);
            }
        }
        #pragma unroll
        for (int t = 0; t < 8; t++) {
            float* wh = sWh + (size_t)(tt*8 + t)*NH + 2*cc;
            *(unsigned long long*)(wh)        = acc[t][0];
            *(unsigned long long*)(wh + 512)  = acc[t][1];
            *(unsigned long long*)(wh + 1024) = acc[t][2];
        }
    }
    __syncthreads();

    // ---- phase 2: out[t][k] = mean_i elu( sum_j attn[t][i][j]*Wh[t][j][k] ) ----
    // f32x2 packed along j-pairs: attn pairs are contiguous -> direct LDS.64
    // broadcast (t uniform per warp). Per (i): 12 LDS.64 + 24 FMA2 for 2 k values.
    {
        const int t = tid >> 5;        // 0..15 (uniform per warp)
        const int g = tid & 31;        // k in {g, g+32}
        const float* whb = sWh + (size_t)t*NH;
        unsigned long long wj[12][2];
        #pragma unroll
        for (int m = 0; m < 12; m++) {
            wj[m][0] = pack2(whb[(2*m)*HH + g],      whb[(2*m+1)*HH + g]);
            wj[m][1] = pack2(whb[(2*m)*HH + g + 32], whb[(2*m+1)*HH + g + 32]);
        }
        const unsigned long long* ap = (const unsigned long long*)(sAttn + t*576);
        float o0 = 0.f, o1 = 0.f;
        #pragma unroll 2
        for (int i = 0; i < NN; i++) {
            unsigned long long s0 = 0ull, s1 = 0ull;   // bits 0 == (0.f, 0.f)
            #pragma unroll
            for (int m = 0; m < 12; m++) {
                unsigned long long av = ap[i*12 + m];
                FMA2(s0, av, wj[m][0]);
                FMA2(s1, av, wj[m][1]);
            }
            float a0, b0, a1, b1;
            unpack2(s0, a0, b0);
            unpack2(s1, a1, b1);
            float v0 = a0 + b0, v1 = a1 + b1;
            o0 += (v0 > 0.f) ? v0 : (__expf(v0) - 1.f);
            o1 += (v1 > 0.f) ? v1 : (__expf(v1) - 1.f);
        }
        const float sc = 1.0f / (float)NN;
        float* ob = out + (size_t)(tok0 + t) * HH;
        ob[g]      = o0 * sc;
        ob[g + 32] = o1 * sc;
    }
}

// ---------------- launch ----------------
extern "C" void kernel_launch(void* const* d_in, const int* in_sizes, int n_in,
                              void* d_out, int out_size) {
    const float* x   = (const float*)d_in[0];
    const int*   adj = (const int*)  d_in[1];
    const float* Wp  = (const float*)d_in[2];
    const float* bp  = (const float*)d_in[3];
    const float* W   = (const float*)d_in[4];
    const float* a   = (const float*)d_in[5];
    float* out = (float*)d_out;

    k_pre<<<FIN, 256>>>(Wp, bp, W, a);

    cudaFuncSetAttribute(k_main, cudaFuncAttributeMaxDynamicSharedMemorySize, SMEM_BYTES);
    k_main<<<GRID, THR, SMEM_BYTES>>>(x, adj, out);
}

// round 11
// speedup vs baseline: 1.6235x; 1.1535x over previous
#include <cuda_runtime.h>
#include <cuda_bf16.h>
#include <cstdint>

// Problem constants
#define NB   16
#define TT   2048
#define FIN  64
#define NN   24
#define HH   64
#define BT   (NB*TT)            // 32768
#define NH   (NN*HH)            // 1536
#define TOK  16                 // tokens per block
#define THR  512
#define AGRID (BT/TOK)          // 2048
#define ALPHA 0.2f
#define NEGINF (-9.0e15f)
#define XS   17                 // padded sX row stride (bank-conflict-free A-frag build)

// ---------------- device globals (no allocs) ----------------
__device__ __align__(16) float g_Wc[FIN*NH];    // [f][col], col = n*64+k
__device__ __align__(16) float g_bc[NH];
__device__ __align__(16) float g_ca1[FIN*NN];
__device__ __align__(16) float g_ca2[FIN*NN];
__device__ float g_cb1[NN];
__device__ float g_cb2[NN];
// B fragments for mma.m16n8k16, pre-split bf16 (term0=hi, term1=lo), fragment-ordered:
// index = ((ct*4 + ks)*2 + term)*32 + lane, each entry 8B = {b0(2xbf16), b1(2xbf16)}
__device__ __align__(16) unsigned long long g_Wfrag[192*4*2*32];   // 384KB

// ---------------- packed fp32x2 helpers ----------------
__device__ __forceinline__ unsigned long long pack2(float lo, float hi) {
    unsigned long long r;
    asm("mov.b64 %0, {%1, %2};" : "=l"(r) : "f"(lo), "f"(hi));
    return r;
}
__device__ __forceinline__ void unpack2u(unsigned long long v, uint32_t& lo, uint32_t& hi) {
    asm("mov.b64 {%0, %1}, %2;" : "=r"(lo), "=r"(hi) : "l"(v));
}
__device__ __forceinline__ void unpack2(unsigned long long v, float& lo, float& hi) {
    asm("mov.b64 {%0, %1}, %2;" : "=f"(lo), "=f"(hi) : "l"(v));
}
#define FMA2(acc, a, b) asm("fma.rn.f32x2 %0, %1, %2, %0;" : "+l"(acc) : "l"(a), "l"(b))

// ---------------- warp mma m16n8k16 bf16 (sm_80+ baseline PTX; no tcgen05) ----------------
__device__ __forceinline__ void mma16816(float& d0, float& d1, float& d2, float& d3,
                                         uint32_t a0, uint32_t a1, uint32_t a2, uint32_t a3,
                                         uint32_t b0, uint32_t b1) {
    asm("mma.sync.aligned.m16n8k16.row.col.f32.bf16.bf16.f32 "
        "{%0,%1,%2,%3}, {%4,%5,%6,%7}, {%8,%9}, {%0,%1,%2,%3};"
        : "+f"(d0), "+f"(d1), "+f"(d2), "+f"(d3)
        : "r"(a0), "r"(a1), "r"(a2), "r"(a3), "r"(b0), "r"(b1));
}
__device__ __forceinline__ uint32_t bpack(__nv_bfloat16 x, __nv_bfloat16 y) {
    __nv_bfloat162 p; p.x = x; p.y = y;
    return *(uint32_t*)&p;
}

// ---------------- merged precompute (unchanged, known-good) ----------------
__global__ void __launch_bounds__(256)
k_pre(const float* __restrict__ Wp, const float* __restrict__ bp,
      const float* __restrict__ W,  const float* __restrict__ a) {
    __shared__ float sW[HH*HH];
    __shared__ float sWp[NH];
    __shared__ float swa1[HH], swa2[HH];
    const int f = blockIdx.x, tid = threadIdx.x;
    for (int i = tid; i < HH*HH; i += 256) sW[i] = W[i];
    for (int i = tid; i < NH;    i += 256) sWp[i] = Wp[f*NH + i];
    __syncthreads();
    if (tid < HH) {
        float s1 = 0.f, s2 = 0.f;
        #pragma unroll 8
        for (int k = 0; k < HH; k++) {
            float wv = sW[tid*HH + k];
            s1 = fmaf(wv, a[k],      s1);
            s2 = fmaf(wv, a[HH + k], s2);
        }
        swa1[tid] = s1; swa2[tid] = s2;
    }
    __syncthreads();
    for (int o = tid; o < NH; o += 256) {
        int n = o >> 6, k = o & 63;
        float s = 0.f;
        #pragma unroll 8
        for (int j = 0; j < HH; j++) s = fmaf(sWp[n*HH + j], sW[j*HH + k], s);
        g_Wc[f*NH + o] = s;
    }
    if (tid < NN) {
        float s1 = 0.f, s2 = 0.f;
        for (int j = 0; j < HH; j++) {
            float wv = sWp[tid*HH + j];
            s1 = fmaf(wv, swa1[j], s1);
            s2 = fmaf(wv, swa2[j], s2);
        }
        g_ca1[f*NN + tid] = s1;
        g_ca2[f*NN + tid] = s2;
    }
    if (tid >= 32 && tid < 32 + NN) {
        int c = f*NN + (tid - 32);
        int n = c >> 6, k = c & 63;
        float s = 0.f;
        #pragma unroll 8
        for (int j = 0; j < HH; j++) s = fmaf(bp[n*HH + j], sW[j*HH + k], s);
        g_bc[c] = s;
    }
    if (f == 0 && tid >= 64 && tid < 64 + NN) {
        int n = tid - 64;
        float s1 = 0.f, s2 = 0.f;
        for (int j = 0; j < HH; j++) {
            float b = bp[n*HH + j];
            s1 = fmaf(b, swa1[j], s1);
            s2 = fmaf(b, swa2[j], s2);
        }
        g_cb1[n] = s1; g_cb2[n] = s2;
    }
}

// ---------------- B-fragment precompute: g_Wc -> g_Wfrag (split bf16, frag order) ------
// Unit u (one 8B entry): lane=u&31, term=(u>>5)&1, ks=(u>>6)&3, ct=u>>8.
// b0 = Wterm[f0, f0+1][col], b1 = Wterm[f0+8, f0+9][col]
// with col = ct*8 + lane/4, f0 = ks*16 + (lane%4)*2  (PTX m16n8k16 B layout)
__global__ void k_frag() {
    int u = blockIdx.x * 256 + threadIdx.x;
    if (u >= 192*4*2*32) return;
    int lane = u & 31;
    int term = (u >> 5) & 1;
    int ks   = (u >> 6) & 3;
    int ct   = u >> 8;
    int col = ct*8 + (lane >> 2);
    int f0  = ks*16 + (lane & 3)*2;
    __nv_bfloat16 e[4];
    #pragma unroll
    for (int r = 0; r < 4; r++) {
        int f = f0 + (r >> 1)*8 + (r & 1);
        float v = g_Wc[f*NH + col];
        __nv_bfloat16 hi = __float2bfloat16(v);
        e[r] = term ? __float2bfloat16(v - __bfloat162float(hi)) : hi;
    }
    uint32_t b0 = bpack(e[0], e[1]);
    uint32_t b1 = bpack(e[2], e[3]);
    g_Wfrag[u] = ((unsigned long long)b1 << 32) | b0;
}

// ---------------- main fused kernel ----------------
// smem layout (bytes):
//  sX    @ 0      : 64 x 17 f32 (f-major, padded)     4608
//  sCa1  @ 4608   : 1536 f32                          6144
//  sCa2  @ 10752  : 1536 f32                          6144
//  sCb1  @ 16896  : 24 f32                            96
//  sCb2  @ 16992  : 24 f32                            96
//  sF1   @ 17088  : 16x24 f32                         1536
//  sF2   @ 18624  : 16x24 f32                         1536
//  sAdj  @ 20160  : 576 i32                           2304
//  sAttn @ 22464  : 16x24x24 f32                      36864
//  sWh   @ 59328  : 16x1536 f32                       98304
//  sBC   @ 157632 : 1536 f32                          6144
#define SMEM_BYTES 163776

__global__ void __launch_bounds__(THR, 1)
k_main(const float* __restrict__ x, const int* __restrict__ adj,
       float* __restrict__ out) {
    extern __shared__ char smem[];
    float* sX    = (float*)(smem);
    float* sCa1  = (float*)(smem + 4608);
    float* sCa2  = (float*)(smem + 10752);
    float* sCb1  = (float*)(smem + 16896);
    float* sCb2  = (float*)(smem + 16992);
    float* sF1   = (float*)(smem + 17088);
    float* sF2   = (float*)(smem + 18624);
    int*   sAdj  = (int*)  (smem + 20160);
    float* sAttn = (float*)(smem + 22464);
    float* sWh   = (float*)(smem + 59328);
    float* sBC   = (float*)(smem + 157632);

    const int tid = threadIdx.x;
    const int tok0 = blockIdx.x * TOK;
    const float* xb = x + (size_t)tok0 * FIN;

    // ---- loads ----
    for (int i = tid; i < TOK*FIN; i += THR) {
        int t = i >> 6, f = i & 63;
        sX[f*XS + t] = xb[i];
    }
    for (int i = tid; i < FIN*NN; i += THR) { sCa1[i] = g_ca1[i]; sCa2[i] = g_ca2[i]; }
    for (int i = tid; i < NH;     i += THR) sBC[i] = g_bc[i];
    if (tid < NN) { sCb1[tid] = g_cb1[tid]; sCb2[tid] = g_cb2[tid]; }
    for (int i = tid; i < NN*NN; i += THR) sAdj[i] = adj[i];
    __syncthreads();

    // ---- f1/f2: 16 tokens x 24 nodes ----
    if (tid < TOK*NN) {
        int t = tid / NN, n = tid % NN;
        float s1 = sCb1[n], s2 = sCb2[n];
        #pragma unroll 8
        for (int f = 0; f < FIN; f++) {
            float xv = sX[f*XS + t];
            s1 = fmaf(xv, sCa1[f*NN + n], s1);
            s2 = fmaf(xv, sCa2[f*NN + n], s2);
        }
        sF1[t*NN + n] = s1;
        sF2[t*NN + n] = s2;
    }
    __syncthreads();

    // ---- softmax rows (warps 0-11); warps 12-15 fall through to mma early ----
    if (tid < TOK*NN) {
        int t = tid / NN, i = tid % NN;
        float f1v = sF1[t*NN + i];
        float ev[NN];
        float m = -3.0e38f;
        #pragma unroll
        for (int j = 0; j < NN; j++) {
            float e = f1v + sF2[t*NN + j];
            e = e > 0.f ? e : ALPHA * e;
            e = (sAdj[i*NN + j] > 0) ? e : NEGINF;
            ev[j] = e;
            m = fmaxf(m, e);
        }
        float sum = 0.f;
        #pragma unroll
        for (int j = 0; j < NN; j++) { float p = __expf(ev[j] - m); ev[j] = p; sum += p; }
        float inv = 1.0f / sum;
        #pragma unroll
        for (int j = 0; j < NN; j++) sAttn[t*576 + i*NN + j] = ev[j] * inv;
    }

    // ---- phase 1: Wh[16][1536] = x @ Wc + bc via mma.m16n8k16 bf16, 3-term split ----
    // warp w owns cols [w*96, w*96+96): 12 n8-tiles. A (x) split into hi/lo frags.
    {
        const int w = tid >> 5, lane = tid & 31;
        const int t0 = lane >> 2;            // A/C row within tile (token)
        const int fq = (lane & 3) * 2;       // A col pair base / C col pair base

        // Build A fragments (hi and lo terms) for all 4 k-steps
        uint32_t ah[4][4], al[4][4];
        #pragma unroll
        for (int ks = 0; ks < 4; ks++) {
            #pragma unroll
            for (int r = 0; r < 4; r++) {
                int f = ks*16 + fq + (r >> 1)*8;   // r=0,1: base cols; r=2,3: +8
                int t = t0 + (r & 1)*8;            // r even: t0; r odd: t0+8
                float v0 = sX[f*XS + t];
                float v1 = sX[(f+1)*XS + t];
                __nv_bfloat16 h0 = __float2bfloat16(v0);
                __nv_bfloat16 h1 = __float2bfloat16(v1);
                ah[ks][r] = bpack(h0, h1);
                al[ks][r] = bpack(__float2bfloat16(v0 - __bfloat162float(h0)),
                                  __float2bfloat16(v1 - __bfloat162float(h1)));
            }
        }

        #pragma unroll 3
        for (int nt = 0; nt < 12; nt++) {
            const int ct = w*12 + nt;
            float d0 = 0.f, d1 = 0.f, d2 = 0.f, d3 = 0.f;
            #pragma unroll
            for (int ks = 0; ks < 4; ks++) {
                unsigned long long bh = __ldg(&g_Wfrag[((ct*4 + ks)*2 + 0)*32 + lane]);
                unsigned long long bl = __ldg(&g_Wfrag[((ct*4 + ks)*2 + 1)*32 + lane]);
                uint32_t bh0, bh1, bl0, bl1;
                unpack2u(bh, bh0, bh1);
                unpack2u(bl, bl0, bl1);
                mma16816(d0, d1, d2, d3, ah[ks][0], ah[ks][1], ah[ks][2], ah[ks][3], bh0, bh1);
                mma16816(d0, d1, d2, d3, ah[ks][0], ah[ks][1], ah[ks][2], ah[ks][3], bl0, bl1);
                mma16816(d0, d1, d2, d3, al[ks][0], al[ks][1], al[ks][2], al[ks][3], bh0, bh1);
            }
            const int col = w*96 + nt*8 + fq;
            float b0 = sBC[col], b1 = sBC[col + 1];
            *(unsigned long long*)&sWh[t0*NH + col]     = pack2(d0 + b0, d1 + b1);
            *(unsigned long long*)&sWh[(t0+8)*NH + col] = pack2(d2 + b0, d3 + b1);
        }
    }
    __syncthreads();

    // ---- phase 2: out[t][k] = mean_i elu( sum_j attn[t][i][j]*Wh[t][j][k] ) ----
    {
        const int t = tid >> 5;        // 0..15 (uniform per warp)
        const int g = tid & 31;        // k in {g, g+32}
        const float* whb = sWh + (size_t)t*NH;
        unsigned long long wj[12][2];
        #pragma unroll
        for (int m = 0; m < 12; m++) {
            wj[m][0] = pack2(whb[(2*m)*HH + g],      whb[(2*m+1)*HH + g]);
            wj[m][1] = pack2(whb[(2*m)*HH + g + 32], whb[(2*m+1)*HH + g + 32]);
        }
        const unsigned long long* ap = (const unsigned long long*)(sAttn + t*576);
        float o0 = 0.f, o1 = 0.f;
        #pragma unroll 2
        for (int i = 0; i < NN; i++) {
            unsigned long long s0 = 0ull, s1 = 0ull;
            #pragma unroll
            for (int m = 0; m < 12; m++) {
                unsigned long long av = ap[i*12 + m];
                FMA2(s0, av, wj[m][0]);
                FMA2(s1, av, wj[m][1]);
            }
            float a0, b0, a1, b1;
            unpack2(s0, a0, b0);
            unpack2(s1, a1, b1);
            float v0 = a0 + b0, v1 = a1 + b1;
            o0 += (v0 > 0.f) ? v0 : (__expf(v0) - 1.f);
            o1 += (v1 > 0.f) ? v1 : (__expf(v1) - 1.f);
        }
        const float sc = 1.0f / (float)NN;
        float* ob = out + (size_t)(tok0 + t) * HH;
        ob[g]      = o0 * sc;
        ob[g + 32] = o1 * sc;
    }
}

// ---------------- launch ----------------
extern "C" void kernel_launch(void* const* d_in, const int* in_sizes, int n_in,
                              void* d_out, int out_size) {
    const float* x   = (const float*)d_in[0];
    const int*   adj = (const int*)  d_in[1];
    const float* Wp  = (const float*)d_in[2];
    const float* bp  = (const float*)d_in[3];
    const float* W   = (const float*)d_in[4];
    const float* a   = (const float*)d_in[5];
    float* out = (float*)d_out;

    k_pre<<<FIN, 256>>>(Wp, bp, W, a);
    k_frag<<<192, 256>>>();

    cudaFuncSetAttribute(k_main, cudaFuncAttributeMaxDynamicSharedMemorySize, SMEM_BYTES);
    k_main<<<AGRID, THR, SMEM_BYTES>>>(x, adj, out);
}